// round 3
// baseline (speedup 1.0000x reference)
#include <cuda_runtime.h>
#include <cstdint>

// out = concat(adj_t @ x, adj_t2 @ x), N=8192, D=256, fp32 via tf32 mma.sync.
// R3: x is pre-converted to tf32 AND column-permuted into g_xperm so the
// mainloop B path is cvt-free and uses conflict-free LDS.128.

constexpr int NN = 8192;
constexpr int DD = 256;
constexpr int BM = 64;
constexpr int BN = 256;
constexpr int BK = 32;
constexpr int NITER = NN / BK;            // 256
constexpr int ASTRIDE = 36;               // A smem row stride (floats)
constexpr int BSTRIDE = 268;              // B smem row stride: 268/4 = 67 = 3 (mod 8)
constexpr int A_ELE = BM * ASTRIDE;       // 2304
constexpr int B_ELE = BK * BSTRIDE;       // 8576
constexpr int STG_FLT = A_ELE + B_ELE;    // 10880
constexpr int SMEM_BYTES = 2 * STG_FLT * 4;  // 87040

// x, tf32-converted + column-permuted, dense [NN][DD]
__device__ float g_xperm[(size_t)NN * DD];

// column-group rotation per (k mod 8); chosen so every B LDS.128 is
// bank-conflict-free with BSTRIDE=268 (verified per 8-lane phase).
__constant__ int c_f[8] = {0, 0, 7, 3, 0, 0, 3, 3};

#define CP_ASYNC16(dst, src) \
    asm volatile("cp.async.cg.shared.global [%0], [%1], 16;" :: "r"(dst), "l"(src))

__device__ __forceinline__ uint32_t smem_u32(const void* p) {
    uint32_t a;
    asm("{ .reg .u64 t; cvta.to.shared.u64 t, %1; cvt.u32.u64 %0, t; }"
        : "=r"(a) : "l"(p));
    return a;
}

__device__ __forceinline__ uint32_t f2tf32(float f) {
    uint32_t r;
    asm("cvt.rna.tf32.f32 %0, %1;" : "=r"(r) : "f"(f));
    return r;
}

__device__ __forceinline__ void mma_tf32(float c[4], const uint32_t a[4],
                                         const uint32_t b0, const uint32_t b1) {
    asm volatile(
        "mma.sync.aligned.m16n8k8.row.col.f32.tf32.tf32.f32 "
        "{%0,%1,%2,%3}, {%4,%5,%6,%7}, {%8,%9}, {%0,%1,%2,%3};"
        : "+f"(c[0]), "+f"(c[1]), "+f"(c[2]), "+f"(c[3])
        : "r"(a[0]), "r"(a[1]), "r"(a[2]), "r"(a[3]), "r"(b0), "r"(b1));
}

// ---------------- prep: x -> tf32 + column permutation ----------------
// stored position of logical column n in row k:
//   blk  = n & 0xC0                      (64-col block)
//   gid  = n & 7, nt = (n >> 3) & 7
//   p    = blk | (((gid + f(k&7)) & 7) << 3) | nt
__global__ void xprep(const float* __restrict__ x) {
    const int k = blockIdx.x;
    const int n = threadIdx.x;
    const int f = c_f[k & 7];
    const int p = (n & 0xC0) | ((((n & 7) + f) & 7) << 3) | ((n >> 3) & 7);
    const float v = x[(size_t)k * DD + n];
    uint32_t t = f2tf32(v);
    g_xperm[(size_t)k * DD + p] = __uint_as_float(t);
}

// ---------------- main GEMM ----------------
__global__ void __launch_bounds__(256, 2) h2gcn_mma(
    const float* __restrict__ adj1,
    const float* __restrict__ adj2,
    float* __restrict__ out)
{
    extern __shared__ float smf[];
    const uint32_t smb = smem_u32(smf);

    const int t    = threadIdx.x;
    const int wid  = t >> 5;
    const int lane = t & 31;
    const int bid  = blockIdx.x;
    const int mat  = bid >> 7;
    const int m0   = (bid & 127) * BM;
    const float* adj = mat ? adj2 : adj1;

    const int wm  = wid & 1;     // 2 warp rows (32 M each)
    const int wn  = wid >> 1;    // 4 warp cols (64 N each)
    const int gid = lane >> 2;
    const int tig = lane & 3;

    // ---- cp.async chunk assignments ----
    const char* aptr[2];
    uint32_t    adst[2];
#pragma unroll
    for (int j = 0; j < 2; j++) {
        int id  = t + 256 * j;
        int row = id >> 3;
        int c   = id & 7;
        aptr[j] = reinterpret_cast<const char*>(adj + (size_t)(m0 + row) * NN) + c * 16;
        adst[j] = (uint32_t)((row * ASTRIDE + c * 4) * 4);
    }
    const char* bptr[8];
    uint32_t    bdst[8];
#pragma unroll
    for (int j = 0; j < 8; j++) {
        int id  = t + 256 * j;
        int row = id >> 6;           // k within tile (0..31)
        int c   = id & 63;           // 16B chunk (stored cols)
        bptr[j] = reinterpret_cast<const char*>(g_xperm + (size_t)row * DD) + c * 16;
        bdst[j] = (uint32_t)((A_ELE + row * BSTRIDE + c * 4) * 4);
    }

    auto load_stage = [&](int buf) {
        const uint32_t sb = smb + (uint32_t)(buf * STG_FLT * 4);
#pragma unroll
        for (int j = 0; j < 2; j++) { CP_ASYNC16(sb + adst[j], aptr[j]); aptr[j] += BK * 4; }
#pragma unroll
        for (int j = 0; j < 8; j++) { CP_ASYNC16(sb + bdst[j], bptr[j]); bptr[j] += (size_t)BK * DD * 4; }
        asm volatile("cp.async.commit_group;");
    };

    float acc[2][8][4];
#pragma unroll
    for (int mt = 0; mt < 2; mt++)
#pragma unroll
        for (int nt = 0; nt < 8; nt++)
#pragma unroll
            for (int i = 0; i < 4; i++) acc[mt][nt][i] = 0.0f;

    // per-thread constant B read column bases (t8 = tig and tig+4)
    const int cb0 = wn * 64 + (((gid + c_f[tig]) & 7) << 3);
    const int cb1 = wn * 64 + (((gid + c_f[tig + 4]) & 7) << 3);
    // per-thread constant A read base
    const int ar0 = (wm * 32 + gid) * ASTRIDE + tig;

    load_stage(0);

    for (int it = 0; it < NITER; it++) {
        if (it + 1 < NITER) {
            load_stage((it + 1) & 1);
            asm volatile("cp.async.wait_group 1;");
        } else {
            asm volatile("cp.async.wait_group 0;");
        }
        __syncthreads();

        const float* sA = smf + (it & 1) * STG_FLT;
        const float* sB = sA + A_ELE;

#pragma unroll
        for (int ks = 0; ks < 4; ks++) {
            const int k = ks * 8;
            // A frags (scalar LDS, conflict-free, + cvt)
            uint32_t a[2][4];
#pragma unroll
            for (int mt = 0; mt < 2; mt++) {
                const int r = ar0 + mt * 16 * ASTRIDE + k;
                a[mt][0] = f2tf32(sA[r]);
                a[mt][1] = f2tf32(sA[r + 8 * ASTRIDE]);
                a[mt][2] = f2tf32(sA[r + 4]);
                a[mt][3] = f2tf32(sA[r + 8 * ASTRIDE + 4]);
            }
            // B frags: 4x LDS.128, already tf32, conflict-free
            const uint4* pb0 = reinterpret_cast<const uint4*>(sB + (k + tig) * BSTRIDE + cb0);
            const uint4* pb1 = reinterpret_cast<const uint4*>(sB + (k + tig + 4) * BSTRIDE + cb1);
            uint4 b0lo = pb0[0], b0hi = pb0[1];
            uint4 b1lo = pb1[0], b1hi = pb1[1];
            const uint32_t b0[8] = {b0lo.x, b0lo.y, b0lo.z, b0lo.w,
                                    b0hi.x, b0hi.y, b0hi.z, b0hi.w};
            const uint32_t b1[8] = {b1lo.x, b1lo.y, b1lo.z, b1lo.w,
                                    b1hi.x, b1hi.y, b1hi.z, b1hi.w};
#pragma unroll
            for (int mt = 0; mt < 2; mt++)
#pragma unroll
                for (int nt = 0; nt < 8; nt++)
                    mma_tf32(acc[mt][nt], a[mt], b0[nt], b1[nt]);
        }
        __syncthreads();
    }

    // Epilogue
    const int colbase = mat * DD + wn * 64 + 2 * tig;
#pragma unroll
    for (int mt = 0; mt < 2; mt++) {
        const int row = m0 + wm * 32 + mt * 16 + gid;
#pragma unroll
        for (int nt = 0; nt < 8; nt++) {
            float* p0 = out + (size_t)row * (2 * DD) + colbase + nt * 8;
            float* p1 = p0 + 8 * (2 * DD);
            *reinterpret_cast<float2*>(p0) = make_float2(acc[mt][nt][0], acc[mt][nt][1]);
            *reinterpret_cast<float2*>(p1) = make_float2(acc[mt][nt][2], acc[mt][nt][3]);
        }
    }
}

extern "C" void kernel_launch(void* const* d_in, const int* in_sizes, int n_in,
                              void* d_out, int out_size) {
    const float* x  = nullptr;
    const float* a1 = nullptr;
    const float* a2 = nullptr;
    for (int i = 0; i < n_in; i++) {
        if (in_sizes[i] == NN * DD)  x  = (const float*)d_in[i];
        else if (!a1)                a1 = (const float*)d_in[i];
        else                         a2 = (const float*)d_in[i];
    }

    static bool attr_set = false;
    if (!attr_set) {
        cudaFuncSetAttribute(h2gcn_mma,
                             cudaFuncAttributeMaxDynamicSharedMemorySize, SMEM_BYTES);
        attr_set = true;
    }

    xprep<<<NN, DD>>>(x);
    h2gcn_mma<<<256, 256, SMEM_BYTES>>>(a1, a2, (float*)d_out);
}

// round 4
// speedup vs baseline: 1.2548x; 1.2548x over previous
#include <cuda_runtime.h>
#include <cstdint>

// out = concat(adj_t @ x, adj_t2 @ x), N=8192, D=256, fp32 via tf32 mma.sync.
// R4: R2 layout (known good), but (a) B pre-converted to tf32 once (g_xt),
// (b) A passed as raw fp32 (HMMA.tf32 ignores low 13 mantissa bits -> trunc),
// (c) single __syncthreads per mainloop iteration.

constexpr int NN = 8192;
constexpr int DD = 256;
constexpr int BM = 64;
constexpr int BK = 32;
constexpr int NITER = NN / BK;            // 256
constexpr int ASTRIDE = 36;               // A smem row stride (floats), conflict-free
constexpr int BSTRIDE = 264;              // B smem row stride (floats), conflict-free
constexpr int A_ELE = BM * ASTRIDE;       // 2304
constexpr int B_ELE = BK * BSTRIDE;       // 8448
constexpr int STG_FLT = A_ELE + B_ELE;    // 10752
constexpr int SMEM_BYTES = 2 * STG_FLT * 4;  // 86016

// x pre-converted to tf32 (rna), same [K, D] layout
__device__ float g_xt[(size_t)NN * DD];

#define CP_ASYNC16(dst, src) \
    asm volatile("cp.async.cg.shared.global [%0], [%1], 16;" :: "r"(dst), "l"(src))

__device__ __forceinline__ uint32_t smem_u32(const void* p) {
    uint32_t a;
    asm("{ .reg .u64 t; cvta.to.shared.u64 t, %1; cvt.u32.u64 %0, t; }"
        : "=r"(a) : "l"(p));
    return a;
}

__device__ __forceinline__ void mma_tf32(float c[4], const uint32_t a[4],
                                         const uint32_t b0, const uint32_t b1) {
    asm volatile(
        "mma.sync.aligned.m16n8k8.row.col.f32.tf32.tf32.f32 "
        "{%0,%1,%2,%3}, {%4,%5,%6,%7}, {%8,%9}, {%0,%1,%2,%3};"
        : "+f"(c[0]), "+f"(c[1]), "+f"(c[2]), "+f"(c[3])
        : "r"(a[0]), "r"(a[1]), "r"(a[2]), "r"(a[3]), "r"(b0), "r"(b1));
}

// ---------------- prep: x -> tf32 (rna), dense copy ----------------
__global__ void xprep(const float* __restrict__ x) {
    const int i = blockIdx.x * 256 + threadIdx.x;
    float v = x[i];
    uint32_t t;
    asm("cvt.rna.tf32.f32 %0, %1;" : "=r"(t) : "f"(v));
    g_xt[i] = __uint_as_float(t);
}

// ---------------- main GEMM ----------------
__global__ void __launch_bounds__(256, 2) h2gcn_mma(
    const float* __restrict__ adj1,
    const float* __restrict__ adj2,
    float* __restrict__ out)
{
    extern __shared__ float smf[];
    const uint32_t smb = smem_u32(smf);

    const int t    = threadIdx.x;
    const int wid  = t >> 5;
    const int lane = t & 31;
    const int bid  = blockIdx.x;
    const int mat  = bid >> 7;                 // 0 -> adj_t, 1 -> adj_t2
    const int m0   = (bid & 127) * BM;
    const float* adj = mat ? adj2 : adj1;

    const int wm  = wid & 1;     // 2 warp rows (32 M each)
    const int wn  = wid >> 1;    // 4 warp cols (64 N each)
    const int gid = lane >> 2;
    const int tig = lane & 3;

    // ---- cp.async chunk assignments (16B chunks) ----
    const char* aptr[2];
    uint32_t    adst[2];
#pragma unroll
    for (int j = 0; j < 2; j++) {
        int id  = t + 256 * j;
        int row = id >> 3;
        int c   = id & 7;
        aptr[j] = reinterpret_cast<const char*>(adj + (size_t)(m0 + row) * NN) + c * 16;
        adst[j] = (uint32_t)((row * ASTRIDE + c * 4) * 4);
    }
    const char* bptr[8];
    uint32_t    bdst[8];
#pragma unroll
    for (int j = 0; j < 8; j++) {
        int id  = t + 256 * j;
        int row = id >> 6;           // k within tile (0..31)
        int c   = id & 63;           // 16B chunk
        bptr[j] = reinterpret_cast<const char*>(g_xt + (size_t)row * DD) + c * 16;
        bdst[j] = (uint32_t)((A_ELE + row * BSTRIDE + c * 4) * 4);
    }

    auto load_stage = [&](int buf) {
        const uint32_t sb = smb + (uint32_t)(buf * STG_FLT * 4);
#pragma unroll
        for (int j = 0; j < 2; j++) { CP_ASYNC16(sb + adst[j], aptr[j]); aptr[j] += BK * 4; }
#pragma unroll
        for (int j = 0; j < 8; j++) { CP_ASYNC16(sb + bdst[j], bptr[j]); bptr[j] += (size_t)BK * DD * 4; }
        asm volatile("cp.async.commit_group;");
    };

    float acc[2][8][4];
#pragma unroll
    for (int mt = 0; mt < 2; mt++)
#pragma unroll
        for (int nt = 0; nt < 8; nt++)
#pragma unroll
            for (int i = 0; i < 4; i++) acc[mt][nt][i] = 0.0f;

    const int ar0 = (wm * 32 + gid) * ASTRIDE + tig;   // A frag base
    const int bc0 = wn * 64 + gid;                      // B frag column base

    load_stage(0);

    for (int it = 0; it < NITER; it++) {
        // stage `it` complete for this thread's copies
        asm volatile("cp.async.wait_group 0;");
        // all warps: stage `it` visible AND compute(it-1) finished (program order)
        __syncthreads();
        // prefetch stage it+1 into the buffer compute(it-1) used — safe post-barrier
        if (it + 1 < NITER) load_stage((it + 1) & 1);

        const float* sA = smf + (it & 1) * STG_FLT;
        const float* sB = sA + A_ELE;

#pragma unroll
        for (int ks = 0; ks < 4; ks++) {
            const int k = ks * 8;
            uint32_t a[2][4];
#pragma unroll
            for (int mt = 0; mt < 2; mt++) {
                const int r = ar0 + mt * 16 * ASTRIDE + k;
                a[mt][0] = __float_as_uint(sA[r]);                 // raw fp32: HMMA
                a[mt][1] = __float_as_uint(sA[r + 8 * ASTRIDE]);   // ignores low 13 bits
                a[mt][2] = __float_as_uint(sA[r + 4]);
                a[mt][3] = __float_as_uint(sA[r + 8 * ASTRIDE + 4]);
            }
            uint32_t b0[8], b1[8];
#pragma unroll
            for (int nt = 0; nt < 8; nt++) {
                const int n = bc0 + nt * 8;
                b0[nt] = __float_as_uint(sB[(k + tig) * BSTRIDE + n]);       // pre-cvt tf32
                b1[nt] = __float_as_uint(sB[(k + tig + 4) * BSTRIDE + n]);
            }
#pragma unroll
            for (int mt = 0; mt < 2; mt++)
#pragma unroll
                for (int nt = 0; nt < 8; nt++)
                    mma_tf32(acc[mt][nt], a[mt], b0[nt], b1[nt]);
        }
    }

    // Epilogue: float2 stores into out[8192, 512] at column offset mat*256
    const int colbase = mat * DD + wn * 64 + 2 * tig;
#pragma unroll
    for (int mt = 0; mt < 2; mt++) {
        const int row = m0 + wm * 32 + mt * 16 + gid;
#pragma unroll
        for (int nt = 0; nt < 8; nt++) {
            float* p0 = out + (size_t)row * (2 * DD) + colbase + nt * 8;
            float* p1 = p0 + 8 * (2 * DD);
            *reinterpret_cast<float2*>(p0) = make_float2(acc[mt][nt][0], acc[mt][nt][1]);
            *reinterpret_cast<float2*>(p1) = make_float2(acc[mt][nt][2], acc[mt][nt][3]);
        }
    }
}

extern "C" void kernel_launch(void* const* d_in, const int* in_sizes, int n_in,
                              void* d_out, int out_size) {
    const float* x  = nullptr;
    const float* a1 = nullptr;
    const float* a2 = nullptr;
    for (int i = 0; i < n_in; i++) {
        if (in_sizes[i] == NN * DD)  x  = (const float*)d_in[i];
        else if (!a1)                a1 = (const float*)d_in[i];
        else                         a2 = (const float*)d_in[i];
    }

    static bool attr_set = false;
    if (!attr_set) {
        cudaFuncSetAttribute(h2gcn_mma,
                             cudaFuncAttributeMaxDynamicSharedMemorySize, SMEM_BYTES);
        attr_set = true;
    }

    xprep<<<(NN * DD) / 256, 256>>>(x);
    h2gcn_mma<<<256, 256, SMEM_BYTES>>>(a1, a2, (float*)d_out);
}

// round 5
// speedup vs baseline: 1.3543x; 1.0793x over previous
#include <cuda_runtime.h>
#include <cstdint>

// out = concat(adj_t @ x, adj_t2 @ x), N=8192, D=256, fp32 via tf32 mma.sync.
// R5: FUSED — one CTA computes both matmuls for its 64-row stripe, so the
// shared B tile (x) is STS'd and LDS'd once per SM instead of twice.
// B pre-converted to tf32 (rna) once; A raw fp32 (HMMA ignores low 13 bits).

constexpr int NN = 8192;
constexpr int DD = 256;
constexpr int BM = 64;
constexpr int BK = 32;
constexpr int NITER = NN / BK;            // 256
constexpr int ASTRIDE = 36;               // A smem row stride (floats), conflict-free
constexpr int BSTRIDE = 264;              // B smem row stride (floats), conflict-free
constexpr int A_ELE = BM * ASTRIDE;       // 2304 floats (per matrix)
constexpr int B_ELE = BK * BSTRIDE;       // 8448 floats
constexpr int STG_FLT = 2 * A_ELE + B_ELE;   // 13056 floats
constexpr int SMEM_BYTES = 2 * STG_FLT * 4;  // 104448 B

// x pre-converted to tf32 (rna), same [K, D] layout
__device__ float g_xt[(size_t)NN * DD];

#define CP_ASYNC16(dst, src) \
    asm volatile("cp.async.cg.shared.global [%0], [%1], 16;" :: "r"(dst), "l"(src))

__device__ __forceinline__ uint32_t smem_u32(const void* p) {
    uint32_t a;
    asm("{ .reg .u64 t; cvta.to.shared.u64 t, %1; cvt.u32.u64 %0, t; }"
        : "=r"(a) : "l"(p));
    return a;
}

__device__ __forceinline__ void mma_tf32(float c[4], const uint32_t a[4],
                                         const uint32_t b0, const uint32_t b1) {
    asm volatile(
        "mma.sync.aligned.m16n8k8.row.col.f32.tf32.tf32.f32 "
        "{%0,%1,%2,%3}, {%4,%5,%6,%7}, {%8,%9}, {%0,%1,%2,%3};"
        : "+f"(c[0]), "+f"(c[1]), "+f"(c[2]), "+f"(c[3])
        : "r"(a[0]), "r"(a[1]), "r"(a[2]), "r"(a[3]), "r"(b0), "r"(b1));
}

// ---------------- prep: x -> tf32 (rna), dense copy ----------------
__global__ void xprep(const float* __restrict__ x) {
    const int i = blockIdx.x * 256 + threadIdx.x;
    float v = x[i];
    uint32_t t;
    asm("cvt.rna.tf32.f32 %0, %1;" : "=r"(t) : "f"(v));
    g_xt[i] = __uint_as_float(t);
}

// ---------------- fused GEMM ----------------
__global__ void __launch_bounds__(256, 1) h2gcn_mma(
    const float* __restrict__ adj1,
    const float* __restrict__ adj2,
    float* __restrict__ out)
{
    extern __shared__ float smf[];
    const uint32_t smb = smem_u32(smf);

    const int t    = threadIdx.x;
    const int wid  = t >> 5;
    const int lane = t & 31;
    const int m0   = blockIdx.x * BM;

    const int wm  = wid & 1;     // 2 warp rows (32 M each)
    const int wn  = wid >> 1;    // 4 warp cols (64 N each)
    const int gid = lane >> 2;
    const int tig = lane & 3;

    // ---- cp.async chunk assignments (16B chunks) ----
    // A1/A2: 64 rows x 8 chunks = 512 each -> 2 per thread per matrix
    // B: 32 rows x 64 chunks = 2048 -> 8 per thread
    const char* aptr[2][2];
    uint32_t    adst[2];
#pragma unroll
    for (int j = 0; j < 2; j++) {
        int id  = t + 256 * j;
        int row = id >> 3;
        int c   = id & 7;
        aptr[0][j] = reinterpret_cast<const char*>(adj1 + (size_t)(m0 + row) * NN) + c * 16;
        aptr[1][j] = reinterpret_cast<const char*>(adj2 + (size_t)(m0 + row) * NN) + c * 16;
        adst[j] = (uint32_t)((row * ASTRIDE + c * 4) * 4);
    }
    const char* bptr[8];
    uint32_t    bdst[8];
#pragma unroll
    for (int j = 0; j < 8; j++) {
        int id  = t + 256 * j;
        int row = id >> 6;           // k within tile (0..31)
        int c   = id & 63;           // 16B chunk
        bptr[j] = reinterpret_cast<const char*>(g_xt + (size_t)row * DD) + c * 16;
        bdst[j] = (uint32_t)((2 * A_ELE + row * BSTRIDE + c * 4) * 4);
    }

    auto load_stage = [&](int buf) {
        const uint32_t sb = smb + (uint32_t)(buf * STG_FLT * 4);
#pragma unroll
        for (int j = 0; j < 2; j++) {
            CP_ASYNC16(sb + adst[j], aptr[0][j]);             aptr[0][j] += BK * 4;
            CP_ASYNC16(sb + A_ELE * 4 + adst[j], aptr[1][j]); aptr[1][j] += BK * 4;
        }
#pragma unroll
        for (int j = 0; j < 8; j++) {
            CP_ASYNC16(sb + bdst[j], bptr[j]);
            bptr[j] += (size_t)BK * DD * 4;
        }
        asm volatile("cp.async.commit_group;");
    };

    float acc[2][2][8][4];   // [mat][mt][nt][i]
#pragma unroll
    for (int g = 0; g < 2; g++)
#pragma unroll
        for (int mt = 0; mt < 2; mt++)
#pragma unroll
            for (int nt = 0; nt < 8; nt++)
#pragma unroll
                for (int i = 0; i < 4; i++) acc[g][mt][nt][i] = 0.0f;

    const int ar0 = (wm * 32 + gid) * ASTRIDE + tig;   // A frag base
    const int bc0 = wn * 64 + gid;                      // B frag column base

    load_stage(0);

    for (int it = 0; it < NITER; it++) {
        asm volatile("cp.async.wait_group 0;");
        __syncthreads();
        if (it + 1 < NITER) load_stage((it + 1) & 1);

        const float* sA1 = smf + (it & 1) * STG_FLT;
        const float* sA2 = sA1 + A_ELE;
        const float* sB  = sA1 + 2 * A_ELE;

#pragma unroll
        for (int ks = 0; ks < 4; ks++) {
            const int k = ks * 8;
            // B frags once — feed both matmuls
            uint32_t b0[8], b1[8];
#pragma unroll
            for (int nt = 0; nt < 8; nt++) {
                const int n = bc0 + nt * 8;
                b0[nt] = __float_as_uint(sB[(k + tig) * BSTRIDE + n]);
                b1[nt] = __float_as_uint(sB[(k + tig + 4) * BSTRIDE + n]);
            }
            // A frags for both matrices
            uint32_t a[2][2][4];
#pragma unroll
            for (int mt = 0; mt < 2; mt++) {
                const int r = ar0 + mt * 16 * ASTRIDE + k;
                a[0][mt][0] = __float_as_uint(sA1[r]);
                a[0][mt][1] = __float_as_uint(sA1[r + 8 * ASTRIDE]);
                a[0][mt][2] = __float_as_uint(sA1[r + 4]);
                a[0][mt][3] = __float_as_uint(sA1[r + 8 * ASTRIDE + 4]);
                a[1][mt][0] = __float_as_uint(sA2[r]);
                a[1][mt][1] = __float_as_uint(sA2[r + 8 * ASTRIDE]);
                a[1][mt][2] = __float_as_uint(sA2[r + 4]);
                a[1][mt][3] = __float_as_uint(sA2[r + 8 * ASTRIDE + 4]);
            }
#pragma unroll
            for (int g = 0; g < 2; g++)
#pragma unroll
                for (int mt = 0; mt < 2; mt++)
#pragma unroll
                    for (int nt = 0; nt < 8; nt++)
                        mma_tf32(acc[g][mt][nt], a[g][mt], b0[nt], b1[nt]);
        }
    }

    // Epilogue: out[8192, 512]; mat g at column offset g*256
#pragma unroll
    for (int g = 0; g < 2; g++) {
        const int colbase = g * DD + wn * 64 + 2 * tig;
#pragma unroll
        for (int mt = 0; mt < 2; mt++) {
            const int row = m0 + wm * 32 + mt * 16 + gid;
#pragma unroll
            for (int nt = 0; nt < 8; nt++) {
                float* p0 = out + (size_t)row * (2 * DD) + colbase + nt * 8;
                float* p1 = p0 + 8 * (2 * DD);
                *reinterpret_cast<float2*>(p0) = make_float2(acc[g][mt][nt][0], acc[g][mt][nt][1]);
                *reinterpret_cast<float2*>(p1) = make_float2(acc[g][mt][nt][2], acc[g][mt][nt][3]);
            }
        }
    }
}

extern "C" void kernel_launch(void* const* d_in, const int* in_sizes, int n_in,
                              void* d_out, int out_size) {
    const float* x  = nullptr;
    const float* a1 = nullptr;
    const float* a2 = nullptr;
    for (int i = 0; i < n_in; i++) {
        if (in_sizes[i] == NN * DD)  x  = (const float*)d_in[i];
        else if (!a1)                a1 = (const float*)d_in[i];
        else                         a2 = (const float*)d_in[i];
    }

    static bool attr_set = false;
    if (!attr_set) {
        cudaFuncSetAttribute(h2gcn_mma,
                             cudaFuncAttributeMaxDynamicSharedMemorySize, SMEM_BYTES);
        attr_set = true;
    }

    xprep<<<(NN * DD) / 256, 256>>>(x);
    h2gcn_mma<<<NN / BM, 256, SMEM_BYTES>>>(a1, a2, (float*)d_out);
}